// round 16
// baseline (speedup 1.0000x reference)
#include <cuda_runtime.h>

// Problem constants: B=256, T=2048, I=2, H=128, 3H=384
#define BB 256
#define TT 2048
#define HH 128
#define NTHREADS 256
#define LCOLS 56            // lower half's columns  [0, 56)
#define UCOLS 72            // upper half's columns  [56, 128)

__device__ int d_order[BB];

// Plain descending-length order (R2-proven best): wave 1 = 148 longest,
// wave-2 CTAs work-stolen in bid order = LPT.
__global__ void order_kernel(const int* __restrict__ lengths) {
    int i = threadIdx.x;
    int li = lengths[i];
    int rank = 0;
    #pragma unroll 8
    for (int j = 0; j < BB; j++) {
        int lj = lengths[j];
        rank += (lj > li) || (lj == li && j < i);
    }
    d_order[rank] = i;
}

// ---- packed f32x2 helpers ----
__device__ __forceinline__ unsigned long long fma2(unsigned long long a,
                                                   unsigned long long b,
                                                   unsigned long long c) {
    unsigned long long d;
    asm("fma.rn.f32x2 %0, %1, %2, %3;" : "=l"(d) : "l"(a), "l"(b), "l"(c));
    return d;
}
__device__ __forceinline__ unsigned long long pack2(float x, float y) {
    unsigned long long r;
    asm("mov.b64 %0, {%1, %2};" : "=l"(r) : "f"(x), "f"(y));
    return r;
}
__device__ __forceinline__ void unpack2(unsigned long long v, float& x, float& y) {
    asm("mov.b64 {%0, %1}, %2;" : "=f"(x), "=f"(y) : "l"(v));
}
__device__ __forceinline__ float tanh_fast(float v) {
    float r;
    asm("tanh.approx.f32 %0, %1;" : "=f"(r) : "f"(v));
    return r;
}

// ASYMMETRIC TRI-ROW SPLIT (R15 champion) + pipe/tail trims:
//   lower (warps 0-3): cols [0,56) of rows r_j,z_j,n_j + gates.
//   upper (warps 4-7): cols [56,128) + publishes {pr,pz,pn,xn}.
//   Hi-wid-first arbiter -> upper's 108 FMA2 drain first; lower's pair-bar
//   sits MID-matvec (after 8/14 blocks) and prefetches p under the
//   remaining FMA2. Single accumulator per gate (R,N,Z interleave gives
//   same-chain distance 9 cyc >= lat). Gate sums/tanhs computed eagerly
//   per-chain so the r->n MUFU chain overlaps aZ's issue; z lands last.
__global__ void __launch_bounds__(NTHREADS, 1)
gru_kernel(const float* __restrict__ x,        // [B, T, 2]
           const int*   __restrict__ lengths,  // [B]
           const float* __restrict__ W_ih,     // [384, 2]
           const float* __restrict__ W_hh,     // [384, 128]
           const float* __restrict__ b_ih,     // [384]
           const float* __restrict__ b_hh,     // [384]
           const float* __restrict__ head_w,   // [128]
           const float* __restrict__ head_b,   // [1]
           float*       __restrict__ out)      // [B, 1]
{
    __shared__ __align__(16) float sh_x[TT * 2 + 4];   // input seq + pad
    __shared__ __align__(16) float sh_h[2][HH];        // ping-pong hidden
    __shared__ __align__(16) float4 sh_p[2][HH];       // ping-pong partials
    __shared__ float sh_red[4];

    const int tid = threadIdx.x;
    const int b = d_order[blockIdx.x];
    const int len = lengths[b];

    const int half = tid >> 7;            // 0 = lower/combiner, 1 = upper
    const int j = tid & 127;
    const int bar_id = 1 + ((tid >> 5) & 3);

    // --- load input prefix into shared ---
    {
        const float4* xs = reinterpret_cast<const float4*>(x + (size_t)b * (TT * 2));
        float4* xd = reinterpret_cast<float4*>(sh_x);
        int nq = (len * 2 + 3) >> 2;
        for (int q = tid; q < nq; q += NTHREADS) xd[q] = xs[q];
        if (tid < 4) sh_x[TT * 2 + tid] = 0.0f;
    }

    if (half) {
        // ================= UPPER: cols [56,128) + xn =======================
        unsigned long long wr[UCOLS / 2], wz[UCOLS / 2], wn[UCOLS / 2];
        {
            const unsigned long long* pr = reinterpret_cast<const unsigned long long*>(
                W_hh + (size_t)j * HH + LCOLS);
            const unsigned long long* pz = reinterpret_cast<const unsigned long long*>(
                W_hh + (size_t)(HH + j) * HH + LCOLS);
            const unsigned long long* pn = reinterpret_cast<const unsigned long long*>(
                W_hh + (size_t)(2 * HH + j) * HH + LCOLS);
            #pragma unroll
            for (int k = 0; k < UCOLS / 2; k++) {
                wr[k] = pr[k]; wz[k] = pz[k]; wn[k] = pn[k];
            }
        }
        // n-row input projection constants (offloaded from lower).
        float nw0, nw1, nb;
        {
            float2 t2 = *reinterpret_cast<const float2*>(W_ih + (size_t)(2 * HH + j) * 2);
            nw0 = t2.x; nw1 = t2.y;
            nb = b_ih[2 * HH + j];
        }
        const unsigned long long zero2 = pack2(0.0f, 0.0f);
        __syncthreads();

        int cur = 0;
        for (int t = 0; t < len; t++) {
            float2 xt = *reinterpret_cast<const float2*>(sh_x + 2 * t);
            float xn = fmaf(nw0, xt.x, fmaf(nw1, xt.y, nb));

            unsigned long long aR = zero2, aZ = zero2, aN = zero2;
            const ulonglong2* hseg =
                reinterpret_cast<const ulonglong2*>(sh_h[cur] + LCOLS);
            #pragma unroll
            for (int k = 0; k < UCOLS / 4; k++) {      // 18 LDS.128
                ulonglong2 hv = hseg[k];
                aR = fma2(wr[2 * k],     hv.x, aR);
                aN = fma2(wn[2 * k],     hv.x, aN);
                aZ = fma2(wz[2 * k],     hv.x, aZ);
                aR = fma2(wr[2 * k + 1], hv.y, aR);
                aN = fma2(wn[2 * k + 1], hv.y, aN);
                aZ = fma2(wz[2 * k + 1], hv.y, aZ);
            }
            float ra, rbv, za, zbv, na, nbv;
            unpack2(aR, ra, rbv);
            unpack2(aZ, za, zbv);
            unpack2(aN, na, nbv);
            sh_p[cur][j] = make_float4(ra + rbv, za + zbv, na + nbv, xn);
            asm volatile("bar.arrive %0, 64;" :: "r"(bar_id) : "memory");
            asm volatile("bar.sync 6, 256;" ::: "memory");   // wait h[56:128)
            cur ^= 1;
        }
    } else {
        // ================= LOWER: cols [0,56) + gates ======================
        unsigned long long wr[LCOLS / 2], wz[LCOLS / 2], wn[LCOLS / 2];
        {
            const unsigned long long* pr = reinterpret_cast<const unsigned long long*>(
                W_hh + (size_t)j * HH);
            const unsigned long long* pz = reinterpret_cast<const unsigned long long*>(
                W_hh + (size_t)(HH + j) * HH);
            const unsigned long long* pn = reinterpret_cast<const unsigned long long*>(
                W_hh + (size_t)(2 * HH + j) * HH);
            #pragma unroll
            for (int k = 0; k < LCOLS / 2; k++) {
                wr[k] = pr[k]; wz[k] = pz[k]; wn[k] = pn[k];
            }
        }
        const unsigned long long bN2 = pack2(b_hh[2 * HH + j], 0.0f);
        const unsigned long long zero2 = pack2(0.0f, 0.0f);

        // sigma prescale (0.5) folded into r,z; both biases folded for r,z.
        float rw0, rw1, rb, zw0, zw1, zb;
        {
            float2 t2 = *reinterpret_cast<const float2*>(W_ih + (size_t)j * 2);
            rw0 = 0.5f * t2.x; rw1 = 0.5f * t2.y;
            rb = 0.5f * (b_ih[j] + b_hh[j]);
            t2 = *reinterpret_cast<const float2*>(W_ih + (size_t)(HH + j) * 2);
            zw0 = 0.5f * t2.x; zw1 = 0.5f * t2.y;
            zb = 0.5f * (b_ih[HH + j] + b_hh[HH + j]);
        }
        float h = 0.0f;
        sh_h[0][j] = 0.0f;
        __syncthreads();

        int cur = 0;
        for (int t = 0; t < len; t++) {
            float2 xt = *reinterpret_cast<const float2*>(sh_x + 2 * t);
            float xr2 = fmaf(rw0, xt.x, fmaf(rw1, xt.y, rb));
            float xz2 = fmaf(zw0, xt.x, fmaf(zw1, xt.y, zb));

            unsigned long long aR = zero2, aZ = zero2, aN = bN2;
            const ulonglong2* hseg =
                reinterpret_cast<const ulonglong2*>(sh_h[cur]);
            // First 8 of 14 h-vector blocks.
            #pragma unroll
            for (int k = 0; k < 8; k++) {
                ulonglong2 hv = hseg[k];
                aR = fma2(wr[2 * k],     hv.x, aR);
                aN = fma2(wn[2 * k],     hv.x, aN);
                aZ = fma2(wz[2 * k],     hv.x, aZ);
                aR = fma2(wr[2 * k + 1], hv.y, aR);
                aN = fma2(wn[2 * k + 1], hv.y, aN);
                aZ = fma2(wz[2 * k + 1], hv.y, aZ);
            }
            // Mid-matvec pair-bar (upper arrived long ago: fall-through) and
            // p prefetch — its 29-cyc latency hides under the last 6 blocks.
            asm volatile("bar.sync %0, 64;" :: "r"(bar_id) : "memory");
            float4 p = sh_p[cur][j];
            #pragma unroll
            for (int k = 8; k < LCOLS / 4; k++) {
                ulonglong2 hv = hseg[k];
                aR = fma2(wr[2 * k],     hv.x, aR);
                aN = fma2(wn[2 * k],     hv.x, aN);
                aZ = fma2(wz[2 * k],     hv.x, aZ);
                aR = fma2(wr[2 * k + 1], hv.y, aR);
                aN = fma2(wn[2 * k + 1], hv.y, aN);
                aZ = fma2(wz[2 * k + 1], hv.y, aZ);
            }
            // Eager per-gate epilogue: r_t and n overlap aZ's issue window.
            float ra, rbv, na, nbv, za, zbv;
            unpack2(aR, ra, rbv);
            float gr = (ra + rbv) + p.x;
            float r_t = tanh_fast(fmaf(0.5f, gr, xr2));
            unpack2(aN, na, nbv);
            float gn = (na + nbv) + p.z;
            float gnh = 0.5f * gn;
            float n = tanh_fast(fmaf(r_t, gnh, p.w + gnh)); // xn from upper
            unpack2(aZ, za, zbv);
            float gz = (za + zbv) + p.y;
            float z_t = tanh_fast(fmaf(0.5f, gz, xz2));
            h = 0.5f * fmaf(z_t, h - n, h + n);             // (1-z)*n + z*h
            sh_h[cur ^ 1][j] = h;
            asm volatile("bar.arrive 6, 256;" ::: "memory"); // upper restart
            asm volatile("bar.sync 5, 128;" ::: "memory");   // lower restart
            cur ^= 1;
        }

        // --- head partial (lower holds h) ---
        float v = h * head_w[j];
        #pragma unroll
        for (int o = 16; o > 0; o >>= 1) v += __shfl_down_sync(0xffffffffu, v, o);
        if ((tid & 31) == 0) sh_red[tid >> 5] = v;
    }

    __syncthreads();
    if (tid == 0) {
        out[b] = (sh_red[0] + sh_red[1]) + (sh_red[2] + sh_red[3]) + head_b[0];
    }
}

extern "C" void kernel_launch(void* const* d_in, const int* in_sizes, int n_in,
                              void* d_out, int out_size) {
    const float* x      = (const float*)d_in[0];
    const int*   len    = (const int*)  d_in[1];
    const float* W_ih   = (const float*)d_in[2];
    const float* W_hh   = (const float*)d_in[3];
    const float* b_ih   = (const float*)d_in[4];
    const float* b_hh   = (const float*)d_in[5];
    const float* head_w = (const float*)d_in[6];
    const float* head_b = (const float*)d_in[7];
    float* out = (float*)d_out;

    order_kernel<<<1, BB>>>(len);
    gru_kernel<<<BB, NTHREADS>>>(x, len, W_ih, W_hh, b_ih, b_hh,
                                 head_w, head_b, out);
}

// round 17
// speedup vs baseline: 1.0330x; 1.0330x over previous
#include <cuda_runtime.h>

// Problem constants: B=256, T=2048, I=2, H=128, 3H=384
#define BB 256
#define TT 2048
#define HH 128
#define NTHREADS 256
#define LCOLS 56            // lower half's columns  [0, 56)
#define UCOLS 72            // upper half's columns  [56, 128)

__device__ int d_order[BB];

// Plain descending-length order (R2-proven best): wave 1 = 148 longest,
// wave-2 CTAs work-stolen in bid order = LPT.
__global__ void order_kernel(const int* __restrict__ lengths) {
    int i = threadIdx.x;
    int li = lengths[i];
    int rank = 0;
    #pragma unroll 8
    for (int j = 0; j < BB; j++) {
        int lj = lengths[j];
        rank += (lj > li) || (lj == li && j < i);
    }
    d_order[rank] = i;
}

// ---- packed f32x2 helpers ----
__device__ __forceinline__ unsigned long long fma2(unsigned long long a,
                                                   unsigned long long b,
                                                   unsigned long long c) {
    unsigned long long d;
    asm("fma.rn.f32x2 %0, %1, %2, %3;" : "=l"(d) : "l"(a), "l"(b), "l"(c));
    return d;
}
__device__ __forceinline__ unsigned long long add2(unsigned long long a,
                                                   unsigned long long b) {
    unsigned long long d;
    asm("add.rn.f32x2 %0, %1, %2;" : "=l"(d) : "l"(a), "l"(b));
    return d;
}
__device__ __forceinline__ unsigned long long pack2(float x, float y) {
    unsigned long long r;
    asm("mov.b64 %0, {%1, %2};" : "=l"(r) : "f"(x), "f"(y));
    return r;
}
__device__ __forceinline__ void unpack2(unsigned long long v, float& x, float& y) {
    asm("mov.b64 {%0, %1}, %2;" : "=f"(x), "=f"(y) : "l"(v));
}
__device__ __forceinline__ float tanh_fast(float v) {
    float r;
    asm("tanh.approx.f32 %0, %1;" : "=f"(r) : "f"(v));
    return r;
}

// ASYMMETRIC TRI-ROW SPLIT (R15 champion structure, unchanged):
//   lower (warps 0-3): cols [0,56) of rows r_j,z_j,n_j + gates. 168 w-regs.
//   upper (warps 4-7): cols [56,128) + publishes {pr,pz,pn,xn}. 216 w-regs.
//   Hi-wid-first arbiter -> upper's 108 FMA2 drain first (~324 cyc); lower's
//   pair-bar (post-matvec, R15 position) is a fall-through.
// R17 deltas vs R15: (1) eager per-gate epilogue — r_t's MUFU launches right
//   after aR's sum so the serial r->n MUFU chain overlaps the z sum tree;
//   (2) upper computes xn into float4.w (lower sheds 2 fma-pipe ops).
// Barriers/step: pair bar 1+w (64 thr) partials upper->lower; bar6 (256,
//   lower arrives post-gate, upper syncs) h for upper restart; bar5 (128,
//   lower-only) h for lower restart. sh_p/sh_h ping-ponged.
__global__ void __launch_bounds__(NTHREADS, 1)
gru_kernel(const float* __restrict__ x,        // [B, T, 2]
           const int*   __restrict__ lengths,  // [B]
           const float* __restrict__ W_ih,     // [384, 2]
           const float* __restrict__ W_hh,     // [384, 128]
           const float* __restrict__ b_ih,     // [384]
           const float* __restrict__ b_hh,     // [384]
           const float* __restrict__ head_w,   // [128]
           const float* __restrict__ head_b,   // [1]
           float*       __restrict__ out)      // [B, 1]
{
    __shared__ __align__(16) float sh_x[TT * 2 + 4];   // input seq + pad
    __shared__ __align__(16) float sh_h[2][HH];        // ping-pong hidden
    __shared__ __align__(16) float4 sh_p[2][HH];       // ping-pong partials
    __shared__ float sh_red[4];

    const int tid = threadIdx.x;
    const int b = d_order[blockIdx.x];
    const int len = lengths[b];

    const int half = tid >> 7;            // 0 = lower/combiner, 1 = upper
    const int j = tid & 127;
    const int bar_id = 1 + ((tid >> 5) & 3);

    // --- load input prefix into shared ---
    {
        const float4* xs = reinterpret_cast<const float4*>(x + (size_t)b * (TT * 2));
        float4* xd = reinterpret_cast<float4*>(sh_x);
        int nq = (len * 2 + 3) >> 2;
        for (int q = tid; q < nq; q += NTHREADS) xd[q] = xs[q];
        if (tid < 4) sh_x[TT * 2 + tid] = 0.0f;
    }

    if (half) {
        // ================= UPPER: cols [56,128) + xn =======================
        unsigned long long wr[UCOLS / 2], wz[UCOLS / 2], wn[UCOLS / 2];
        {
            const unsigned long long* pr = reinterpret_cast<const unsigned long long*>(
                W_hh + (size_t)j * HH + LCOLS);
            const unsigned long long* pz = reinterpret_cast<const unsigned long long*>(
                W_hh + (size_t)(HH + j) * HH + LCOLS);
            const unsigned long long* pn = reinterpret_cast<const unsigned long long*>(
                W_hh + (size_t)(2 * HH + j) * HH + LCOLS);
            #pragma unroll
            for (int k = 0; k < UCOLS / 2; k++) {
                wr[k] = pr[k]; wz[k] = pz[k]; wn[k] = pn[k];
            }
        }
        // n-row input projection constants (offloaded from lower).
        float nw0, nw1, nb;
        {
            float2 t2 = *reinterpret_cast<const float2*>(W_ih + (size_t)(2 * HH + j) * 2);
            nw0 = t2.x; nw1 = t2.y;
            nb = b_ih[2 * HH + j];
        }
        const unsigned long long zero2 = pack2(0.0f, 0.0f);
        __syncthreads();

        int cur = 0;
        for (int t = 0; t < len; t++) {
            float2 xt = *reinterpret_cast<const float2*>(sh_x + 2 * t);
            float xn = fmaf(nw0, xt.x, fmaf(nw1, xt.y, nb));

            unsigned long long aR0 = zero2, aR1 = zero2;
            unsigned long long aZ0 = zero2, aZ1 = zero2;
            unsigned long long aN0 = zero2, aN1 = zero2;
            const ulonglong2* hseg =
                reinterpret_cast<const ulonglong2*>(sh_h[cur] + LCOLS);
            #pragma unroll
            for (int k = 0; k < UCOLS / 4; k++) {      // 18 LDS.128
                ulonglong2 hv = hseg[k];
                aR0 = fma2(wr[2 * k],     hv.x, aR0);
                aZ0 = fma2(wz[2 * k],     hv.x, aZ0);
                aN0 = fma2(wn[2 * k],     hv.x, aN0);
                aR1 = fma2(wr[2 * k + 1], hv.y, aR1);
                aZ1 = fma2(wz[2 * k + 1], hv.y, aZ1);
                aN1 = fma2(wn[2 * k + 1], hv.y, aN1);
            }
            unsigned long long sR = add2(aR0, aR1);
            unsigned long long sZ = add2(aZ0, aZ1);
            unsigned long long sN = add2(aN0, aN1);
            float ra, rbv, za, zbv, na, nbv;
            unpack2(sR, ra, rbv);
            unpack2(sZ, za, zbv);
            unpack2(sN, na, nbv);
            sh_p[cur][j] = make_float4(ra + rbv, za + zbv, na + nbv, xn);
            asm volatile("bar.arrive %0, 64;" :: "r"(bar_id) : "memory");
            asm volatile("bar.sync 6, 256;" ::: "memory");   // wait h[56:128)
            cur ^= 1;
        }
    } else {
        // ================= LOWER: cols [0,56) + gates ======================
        unsigned long long wr[LCOLS / 2], wz[LCOLS / 2], wn[LCOLS / 2];
        {
            const unsigned long long* pr = reinterpret_cast<const unsigned long long*>(
                W_hh + (size_t)j * HH);
            const unsigned long long* pz = reinterpret_cast<const unsigned long long*>(
                W_hh + (size_t)(HH + j) * HH);
            const unsigned long long* pn = reinterpret_cast<const unsigned long long*>(
                W_hh + (size_t)(2 * HH + j) * HH);
            #pragma unroll
            for (int k = 0; k < LCOLS / 2; k++) {
                wr[k] = pr[k]; wz[k] = pz[k]; wn[k] = pn[k];
            }
        }
        const unsigned long long bN2 = pack2(b_hh[2 * HH + j], 0.0f);
        const unsigned long long zero2 = pack2(0.0f, 0.0f);

        // sigma prescale (0.5) folded into r,z; both biases folded for r,z.
        float rw0, rw1, rb, zw0, zw1, zb;
        {
            float2 t2 = *reinterpret_cast<const float2*>(W_ih + (size_t)j * 2);
            rw0 = 0.5f * t2.x; rw1 = 0.5f * t2.y;
            rb = 0.5f * (b_ih[j] + b_hh[j]);
            t2 = *reinterpret_cast<const float2*>(W_ih + (size_t)(HH + j) * 2);
            zw0 = 0.5f * t2.x; zw1 = 0.5f * t2.y;
            zb = 0.5f * (b_ih[HH + j] + b_hh[HH + j]);
        }
        float h = 0.0f;
        sh_h[0][j] = 0.0f;
        __syncthreads();

        int cur = 0;
        for (int t = 0; t < len; t++) {
            float2 xt = *reinterpret_cast<const float2*>(sh_x + 2 * t);
            float xr2 = fmaf(rw0, xt.x, fmaf(rw1, xt.y, rb));
            float xz2 = fmaf(zw0, xt.x, fmaf(zw1, xt.y, zb));

            unsigned long long aR0 = zero2, aR1 = zero2;
            unsigned long long aZ0 = zero2, aZ1 = zero2;
            unsigned long long aN0 = bN2,  aN1 = zero2;
            const ulonglong2* hseg =
                reinterpret_cast<const ulonglong2*>(sh_h[cur]);
            #pragma unroll
            for (int k = 0; k < LCOLS / 4; k++) {      // 14 LDS.128
                ulonglong2 hv = hseg[k];
                aR0 = fma2(wr[2 * k],     hv.x, aR0);
                aZ0 = fma2(wz[2 * k],     hv.x, aZ0);
                aN0 = fma2(wn[2 * k],     hv.x, aN0);
                aR1 = fma2(wr[2 * k + 1], hv.y, aR1);
                aZ1 = fma2(wz[2 * k + 1], hv.y, aZ1);
                aN1 = fma2(wn[2 * k + 1], hv.y, aN1);
            }

            // Upper published ~250 cyc ago: fast-path sync, then p load.
            asm volatile("bar.sync %0, 64;" :: "r"(bar_id) : "memory");
            float4 p = sh_p[cur][j];

            // Eager per-gate epilogue: r first (its MUFU overlaps the n/z
            // sum trees), then n (needs r_t), z last.
            unsigned long long sR = add2(aR0, aR1);
            float ra, rbv;
            unpack2(sR, ra, rbv);
            float gr = (ra + rbv) + p.x;
            float r_t = tanh_fast(fmaf(0.5f, gr, xr2));

            unsigned long long sN = add2(aN0, aN1);
            float na, nbv;
            unpack2(sN, na, nbv);
            float gn = (na + nbv) + p.z;
            float gnh = 0.5f * gn;
            float n = tanh_fast(fmaf(r_t, gnh, p.w + gnh)); // xn from upper

            unsigned long long sZ = add2(aZ0, aZ1);
            float za, zbv;
            unpack2(sZ, za, zbv);
            float gz = (za + zbv) + p.y;
            float z_t = tanh_fast(fmaf(0.5f, gz, xz2));

            h = 0.5f * fmaf(z_t, h - n, h + n);             // (1-z)*n + z*h
            sh_h[cur ^ 1][j] = h;
            asm volatile("bar.arrive 6, 256;" ::: "memory"); // upper restart
            asm volatile("bar.sync 5, 128;" ::: "memory");   // lower restart
            cur ^= 1;
        }

        // --- head partial (lower holds h) ---
        float v = h * head_w[j];
        #pragma unroll
        for (int o = 16; o > 0; o >>= 1) v += __shfl_down_sync(0xffffffffu, v, o);
        if ((tid & 31) == 0) sh_red[tid >> 5] = v;
    }

    __syncthreads();
    if (tid == 0) {
        out[b] = (sh_red[0] + sh_red[1]) + (sh_red[2] + sh_red[3]) + head_b[0];
    }
}

extern "C" void kernel_launch(void* const* d_in, const int* in_sizes, int n_in,
                              void* d_out, int out_size) {
    const float* x      = (const float*)d_in[0];
    const int*   len    = (const int*)  d_in[1];
    const float* W_ih   = (const float*)d_in[2];
    const float* W_hh   = (const float*)d_in[3];
    const float* b_ih   = (const float*)d_in[4];
    const float* b_hh   = (const float*)d_in[5];
    const float* head_w = (const float*)d_in[6];
    const float* head_b = (const float*)d_in[7];
    float* out = (float*)d_out;

    order_kernel<<<1, BB>>>(len);
    gru_kernel<<<BB, NTHREADS>>>(x, len, W_ih, W_hh, b_ih, b_hh,
                                 head_w, head_b, out);
}